// round 16
// baseline (speedup 1.0000x reference)
#include <cuda_runtime.h>
#include <cuda_bf16.h>
#include <cuda_fp16.h>
#include <cstdint>
#include <cstddef>

#define Bq   2
#define Sq   2048
#define HIDD 2048
#define NH   32
#define NKV  8
#define HD   64
#define QKVW ((NH + 2 * NKV) * HD)   /* 3072 */
#define GROUP (NH / NKV)             /* 4 */
#define SCALE 0.125f
#define LOG2E 1.4426950408889634f
#define QSCALE (SCALE * LOG2E)
#define ROPE_C 0.28782313662425575f  /* ln(10000)/32 */

#define MROWS   (Bq * Sq)            /* 4096 */
#define N_HID   (NH * HD)            /* 2048 */

// ---------------------------------------------------------------------------
// Scratch (device globals)
// ---------------------------------------------------------------------------
__device__ __half g_hid_hi [(size_t)MROWS * HIDD];
__device__ __half g_hid_lo [(size_t)MROWS * HIDD];
__device__ __half g_wqkvT  [(size_t)QKVW * HIDD];
__device__ __half g_woT    [(size_t)HIDD * N_HID];
__device__ __half g_attn_hi[(size_t)MROWS * N_HID];
__device__ __half g_attn_lo[(size_t)MROWS * N_HID];

// Q (RoPE'd, scaled) bf16 hi/lo: [b, h, s, d]
__device__ __nv_bfloat16 g_q_hi [(size_t)Bq * NH * Sq * HD];
__device__ __nv_bfloat16 g_q_lo [(size_t)Bq * NH * Sq * HD];
// K (RoPE'd) bf16 hi/lo: [b, hk, s, d]; V^T fp16: [b, hk, d, s]
__device__ __nv_bfloat16 g_k_hi [(size_t)Bq * NKV * Sq * HD];
__device__ __nv_bfloat16 g_k_lo [(size_t)Bq * NKV * Sq * HD];
__device__ __half        g_vt   [(size_t)Bq * NKV * HD * Sq];

// ---------------------------------------------------------------------------
// Helpers
// ---------------------------------------------------------------------------
__device__ __forceinline__ uint32_t smem_u32(const void* p) {
    uint32_t a;
    asm("{ .reg .u64 t; cvta.to.shared.u64 t, %1; cvt.u32.u64 %0, t; }"
        : "=r"(a) : "l"(p));
    return a;
}
__device__ __forceinline__ uint32_t packbf(float x, float y) {   // lo=x, hi=y
    uint32_t r;
    asm("cvt.rn.bf16x2.f32 %0, %1, %2;" : "=r"(r) : "f"(y), "f"(x));
    return r;
}
__device__ __forceinline__ float2 unpackbf(uint32_t v) {
    __nv_bfloat162 t = *reinterpret_cast<__nv_bfloat162*>(&v);
    return make_float2(__bfloat162float(t.x), __bfloat162float(t.y));
}
__device__ __forceinline__ uint32_t packh(float x, float y) {    // lo=x, hi=y
    uint32_t r;
    asm("cvt.rn.f16x2.f32 %0, %1, %2;" : "=r"(r) : "f"(y), "f"(x));
    return r;
}
__device__ __forceinline__ float2 unpackh(uint32_t v) {
    __half2 t = *reinterpret_cast<__half2*>(&v);
    return make_float2(__half2float(t.x), __half2float(t.y));
}
__device__ __forceinline__ float ex2(float x) {
    float r; asm("ex2.approx.f32 %0, %1;" : "=f"(r) : "f"(x)); return r;
}

#define MMA_BF16(c, a, br0, br1) \
    asm volatile("mma.sync.aligned.m16n8k16.row.col.f32.bf16.bf16.f32 " \
        "{%0,%1,%2,%3}, {%4,%5,%6,%7}, {%8,%9}, {%0,%1,%2,%3};" \
        : "+f"((c)[0]), "+f"((c)[1]), "+f"((c)[2]), "+f"((c)[3]) \
        : "r"((a)[0]), "r"((a)[1]), "r"((a)[2]), "r"((a)[3]), "r"(br0), "r"(br1))

#define MMA_F16(c, a, br0, br1) \
    asm volatile("mma.sync.aligned.m16n8k16.row.col.f32.f16.f16.f32 " \
        "{%0,%1,%2,%3}, {%4,%5,%6,%7}, {%8,%9}, {%0,%1,%2,%3};" \
        : "+f"((c)[0]), "+f"((c)[1]), "+f"((c)[2]), "+f"((c)[3]) \
        : "r"((a)[0]), "r"((a)[1]), "r"((a)[2]), "r"((a)[3]), "r"(br0), "r"(br1))

#define LDMATRIX_X4(r, addr) \
    asm volatile("ldmatrix.sync.aligned.m8n8.x4.shared.b16 {%0,%1,%2,%3}, [%4];" \
        : "=r"((r)[0]), "=r"((r)[1]), "=r"((r)[2]), "=r"((r)[3]) : "r"(addr))

#define CP_ASYNC16(saddr, gptr) \
    asm volatile("cp.async.cg.shared.global [%0], [%1], 16;" :: "r"(saddr), "l"(gptr))
#define CP_COMMIT() asm volatile("cp.async.commit_group;" ::: "memory")
template <int N> __device__ __forceinline__ void cp_wait() {
    asm volatile("cp.async.wait_group %0;" :: "n"(N) : "memory");
}

// ---------------------------------------------------------------------------
// fp32 -> fp16 hi/lo split
// ---------------------------------------------------------------------------
__global__ void convert_split_h(const float* __restrict__ x,
                                __half* __restrict__ hi,
                                __half* __restrict__ lo, int n4)
{
    int i = blockIdx.x * blockDim.x + threadIdx.x;
    if (i >= n4) return;
    float4 v = ((const float4*)x)[i];
    uint32_t h01 = packh(v.x, v.y), h23 = packh(v.z, v.w);
    float2 f01 = unpackh(h01), f23 = unpackh(h23);
    uint32_t l01 = packh(v.x - f01.x, v.y - f01.y);
    uint32_t l23 = packh(v.z - f23.x, v.w - f23.y);
    ((uint2*)hi)[i] = make_uint2(h01, h23);
    ((uint2*)lo)[i] = make_uint2(l01, l23);
}

// ---------------------------------------------------------------------------
// Transpose fp32 B[R x C] -> fp16 [C x R]
// ---------------------------------------------------------------------------
__global__ void transpose_h(const float* __restrict__ B,
                            __half* __restrict__ T, int R, int C)
{
    __shared__ float t[32][33];
    int x = blockIdx.x * 32 + threadIdx.x;
    int y = blockIdx.y * 32 + threadIdx.y;
    #pragma unroll
    for (int j = 0; j < 32; j += 8)
        t[threadIdx.y + j][threadIdx.x] = B[(size_t)(y + j) * C + x];
    __syncthreads();
    int ox = blockIdx.y * 32 + threadIdx.x;
    int oy = blockIdx.x * 32 + threadIdx.y;
    #pragma unroll
    for (int j = 0; j < 32; j += 8)
        T[(size_t)(oy + j) * R + ox] = __float2half_rn(t[threadIdx.x][threadIdx.y + j]);
}

// ---------------------------------------------------------------------------
// Persistent GEMM: C = (Ahi+Alo) * B^T (fp16 2-product).
// 3-stage smem ring, K-chunk 32, TWO cp.async groups in flight (cp_wait<1>).
// fuse_kv epilogue: Q RoPE+scale+bf16 split, K RoPE+bf16 split, V transpose.
// ---------------------------------------------------------------------------
#define ROWB       80            /* 64B data + 16B pad */
#define TILEB      (128 * ROWB)  /* 10240 */
#define STAGEB     (3 * TILEB)   /* 30720: Ahi, Alo, B */
#define GEMM_SMEM  (3 * STAGEB)  /* 92160 */

__global__ __launch_bounds__(256, 2) void gemm_h(
    int M, int N, int K,
    const __half* __restrict__ Ahi, const __half* __restrict__ Alo,
    const __half* __restrict__ B,
    float* __restrict__ C,
    const int* __restrict__ positions, int fuse_kv)
{
    extern __shared__ char smem[];
    const uint32_t sbase = smem_u32(smem);
    const int tid  = threadIdx.x;
    const int wid  = tid >> 5;
    const int lane = tid & 31;
    const int wm = (wid >> 1) * 32;
    const int wn = (wid & 1) * 64;

    const int q  = lane >> 3;
    const int ri = lane & 7;
    const int a_row_add = ((q & 1) << 3) + ri;
    const int a_col_add = (q >> 1) << 3;
    const int b_row_add = ((q >> 1) << 3) + ri;
    const int b_col_add = (q & 1) << 3;
    const int go = lane >> 2;
    const int tg = lane & 3;

    const int nx = N >> 7;
    const int ntiles = (M >> 7) * nx;
    const int NC = K >> 5;   // chunks of 32

    for (int tile = blockIdx.x; tile < ntiles; tile += gridDim.x) {
        const int m0 = (tile / nx) * 128;
        const int n0 = (tile % nx) * 128;

        const __half* srcs[3] = {
            Ahi + (size_t)m0 * K, Alo + (size_t)m0 * K, B + (size_t)n0 * K
        };

        float acc[2][8][4];
        #pragma unroll
        for (int mi = 0; mi < 2; mi++)
            #pragma unroll
            for (int ni = 0; ni < 8; ni++)
                #pragma unroll
                for (int c = 0; c < 4; c++) acc[mi][ni][c] = 0.f;

        auto load_chunk = [&](int stage, int k0) {
            uint32_t sdst = sbase + stage * STAGEB;
            #pragma unroll
            for (int t = 0; t < 3; t++) {
                #pragma unroll
                for (int u = 0; u < 2; u++) {
                    int idx = tid + u * 256;        // 0..511
                    int row = idx >> 2;
                    int seg = idx & 3;
                    const __half* g = srcs[t] + (size_t)row * K + k0 + seg * 8;
                    CP_ASYNC16(sdst + t * TILEB + row * ROWB + seg * 16, g);
                }
            }
            CP_COMMIT();
        };

        __syncthreads();   // smem ring reuse across tiles
        load_chunk(0, 0);
        load_chunk(1, 32);

        for (int i = 0; i < NC; i++) {
            if (i + 1 < NC) cp_wait<1>();   // oldest group (chunk i) complete
            else            cp_wait<0>();
            __syncthreads();
            if (i + 2 < NC) load_chunk((i + 2) % 3, (i + 2) << 5);

            const uint32_t st = sbase + (i % 3) * STAGEB;
            #pragma unroll
            for (int kk = 0; kk < 32; kk += 16) {
                uint32_t a_hi[2][4], a_lo[2][4];
                #pragma unroll
                for (int mi = 0; mi < 2; mi++) {
                    int row = wm + mi * 16 + a_row_add;
                    int col = kk + a_col_add;
                    LDMATRIX_X4(a_hi[mi], st + 0 * TILEB + row * ROWB + col * 2);
                    LDMATRIX_X4(a_lo[mi], st + 1 * TILEB + row * ROWB + col * 2);
                }
                #pragma unroll
                for (int nj = 0; nj < 4; nj++) {
                    uint32_t bf[4];
                    int row = wn + nj * 16 + b_row_add;
                    int col = kk + b_col_add;
                    LDMATRIX_X4(bf, st + 2 * TILEB + row * ROWB + col * 2);
                    #pragma unroll
                    for (int mi = 0; mi < 2; mi++) {
                        #pragma unroll
                        for (int hh = 0; hh < 2; hh++) {
                            int ni = nj * 2 + hh;
                            MMA_F16(acc[mi][ni], a_hi[mi], bf[hh*2], bf[hh*2+1]);
                            MMA_F16(acc[mi][ni], a_lo[mi], bf[hh*2], bf[hh*2+1]);
                        }
                    }
                }
            }
        }

        // ------------------- epilogue -------------------
        const int colbase = n0 + wn;       // warp's 64-col region start
        if (!fuse_kv) {
            #pragma unroll
            for (int mi = 0; mi < 2; mi++) {
                #pragma unroll
                for (int ni = 0; ni < 8; ni++) {
                    int row = m0 + wm + mi * 16 + go;
                    int col = n0 + wn + ni * 8 + tg * 2;
                    *(float2*)(C + (size_t)row * N + col)       = make_float2(acc[mi][ni][0], acc[mi][ni][1]);
                    *(float2*)(C + (size_t)(row + 8) * N + col) = make_float2(acc[mi][ni][2], acc[mi][ni][3]);
                }
            }
        } else if (colbase < NH * HD) {
            // Q region: RoPE + QSCALE + bf16 hi/lo to [b, h, s, d]
            const int hq = colbase >> 6;
            #pragma unroll
            for (int mi = 0; mi < 2; mi++) {
                #pragma unroll
                for (int rs = 0; rs < 2; rs++) {
                    int m = m0 + wm + mi * 16 + go + rs * 8;
                    float pos = (float)positions[m];
                    int bb = m >> 11, ss = m & (Sq - 1);
                    size_t qb = ((size_t)(bb * NH + hq) * Sq + ss) * HD;
                    #pragma unroll
                    for (int ni = 0; ni < 4; ni++) {
                        int d0 = ni * 8 + tg * 2;
                        float x1a = acc[mi][ni][rs * 2 + 0],     x1b = acc[mi][ni][rs * 2 + 1];
                        float x2a = acc[mi][ni + 4][rs * 2 + 0], x2b = acc[mi][ni + 4][rs * 2 + 1];
                        float sna, csa, snb, csb;
                        sincosf(pos * __expf(-(float)d0 * ROPE_C), &sna, &csa);
                        sincosf(pos * __expf(-(float)(d0 + 1) * ROPE_C), &snb, &csb);
                        float o1a = (x1a * csa - x2a * sna) * QSCALE, o2a = (x2a * csa + x1a * sna) * QSCALE;
                        float o1b = (x1b * csb - x2b * snb) * QSCALE, o2b = (x2b * csb + x1b * snb) * QSCALE;
                        uint32_t h1 = packbf(o1a, o1b); float2 u1 = unpackbf(h1);
                        uint32_t h2 = packbf(o2a, o2b); float2 u2 = unpackbf(h2);
                        *(uint32_t*)(g_q_hi + qb + d0)      = h1;
                        *(uint32_t*)(g_q_lo + qb + d0)      = packbf(o1a - u1.x, o1b - u1.y);
                        *(uint32_t*)(g_q_hi + qb + d0 + 32) = h2;
                        *(uint32_t*)(g_q_lo + qb + d0 + 32) = packbf(o2a - u2.x, o2b - u2.y);
                    }
                }
            }
        } else if (colbase < (NH + NKV) * HD) {
            // K region: RoPE + bf16 hi/lo direct write
            const int hk = (colbase - NH * HD) >> 6;
            #pragma unroll
            for (int mi = 0; mi < 2; mi++) {
                #pragma unroll
                for (int rs = 0; rs < 2; rs++) {
                    int m = m0 + wm + mi * 16 + go + rs * 8;
                    float pos = (float)positions[m];
                    int bb = m >> 11, ss = m & (Sq - 1);
                    size_t kb = ((size_t)(bb * NKV + hk) * Sq + ss) * HD;
                    #pragma unroll
                    for (int ni = 0; ni < 4; ni++) {
                        int d0 = ni * 8 + tg * 2;
                        float x1a = acc[mi][ni][rs * 2 + 0],     x1b = acc[mi][ni][rs * 2 + 1];
                        float x2a = acc[mi][ni + 4][rs * 2 + 0], x2b = acc[mi][ni + 4][rs * 2 + 1];
                        float sna, csa, snb, csb;
                        sincosf(pos * __expf(-(float)d0 * ROPE_C), &sna, &csa);
                        sincosf(pos * __expf(-(float)(d0 + 1) * ROPE_C), &snb, &csb);
                        float o1a = x1a * csa - x2a * sna, o2a = x2a * csa + x1a * sna;
                        float o1b = x1b * csb - x2b * snb, o2b = x2b * csb + x1b * snb;
                        uint32_t h1 = packbf(o1a, o1b); float2 u1 = unpackbf(h1);
                        uint32_t h2 = packbf(o2a, o2b); float2 u2 = unpackbf(h2);
                        *(uint32_t*)(g_k_hi + kb + d0)      = h1;
                        *(uint32_t*)(g_k_lo + kb + d0)      = packbf(o1a - u1.x, o1b - u1.y);
                        *(uint32_t*)(g_k_hi + kb + d0 + 32) = h2;
                        *(uint32_t*)(g_k_lo + kb + d0 + 32) = packbf(o2a - u2.x, o2b - u2.y);
                    }
                }
            }
        } else {
            // V region: transposed single-fp16 write
            const int hk = (colbase - (NH + NKV) * HD) >> 6;
            #pragma unroll
            for (int mi = 0; mi < 2; mi++) {
                #pragma unroll
                for (int rs = 0; rs < 2; rs++) {
                    int m = m0 + wm + mi * 16 + go + rs * 8;
                    int bb = m >> 11, ss = m & (Sq - 1);
                    size_t vb = (size_t)(bb * NKV + hk) * HD * Sq + ss;
                    #pragma unroll
                    for (int ni = 0; ni < 8; ni++) {
                        int d0 = ni * 8 + tg * 2;
                        g_vt[vb + (size_t)d0 * Sq]       = __float2half_rn(acc[mi][ni][rs * 2 + 0]);
                        g_vt[vb + (size_t)(d0 + 1) * Sq] = __float2half_rn(acc[mi][ni][rs * 2 + 1]);
                    }
                }
            }
        }
    }
}

// ---------------------------------------------------------------------------
// mma.sync flash attention; Q pre-RoPE'd/scaled/split by the QKV GEMM.
// ---------------------------------------------------------------------------
#define ATT_KROWB  144
#define ATT_KTILE  (128 * ATT_KROWB)
#define ATT_VROWB  272
#define ATT_VTILE  (64 * ATT_VROWB)
#define ATT_VOFF   (2 * ATT_KTILE)
#define ATT_STAGEB (ATT_VOFF + ATT_VTILE)
#define ATT_SMEM   (2 * ATT_STAGEB)

__global__ __launch_bounds__(256, 1) void attn_mma()
{
    const int qt = (int)gridDim.x - 1 - (int)blockIdx.x;
    const int h  = blockIdx.y;
    const int b  = blockIdx.z;
    const int hk = h / GROUP;
    const int q0 = qt * 128;

    extern __shared__ char smem[];
    const uint32_t sb = smem_u32(smem);
    const int tid  = threadIdx.x;
    const int wid  = tid >> 5;
    const int lane = tid & 31;
    const int wm   = wid * 16;
    const int g  = lane >> 2;
    const int tg = lane & 3;
    const int q  = lane >> 3;
    const int ri = lane & 7;
    const int b_row_add = ((q >> 1) << 3) + ri;
    const int b_col_add = (q & 1) << 3;

    // ---- Q fragments: direct uint32 loads ----
    uint32_t qa_hi[4][4], qa_lo[4][4];
    {
        size_t qb = ((size_t)(b * NH + h) * Sq + q0 + wm) * HD;
        #pragma unroll
        for (int kb = 0; kb < 4; kb++) {
            #pragma unroll
            for (int p = 0; p < 4; p++) {
                int row = g + (p & 1) * 8;
                int col = kb * 16 + tg * 2 + ((p >> 1) << 3);
                size_t off = qb + (size_t)row * HD + col;
                qa_hi[kb][p] = *(const uint32_t*)(g_q_hi + off);
                qa_lo[kb][p] = *(const uint32_t*)(g_q_lo + off);
            }
        }
    }

    float oacc[8][4];
    #pragma unroll
    for (int n = 0; n < 8; n++)
        #pragma unroll
        for (int j = 0; j < 4; j++) oacc[n][j] = 0.f;
    float m0 = -1e30f, m1 = -1e30f, l0 = 0.f, l1 = 0.f;

    const __nv_bfloat16* khi = g_k_hi + (size_t)(b * NKV + hk) * Sq * HD;
    const __nv_bfloat16* klo = g_k_lo + (size_t)(b * NKV + hk) * Sq * HD;
    const __half*        vts = g_vt   + (size_t)(b * NKV + hk) * HD * Sq;

    const int nchunks = qt + 1;

    auto load = [&](int stg, int ct) {
        uint32_t dst = sb + stg * ATT_STAGEB;
        int j0 = ct * 128;
        #pragma unroll
        for (int k = 0; k < 12; k++) {
            int c = tid + k * 256;
            if (c < 2048) {
                int t = c >> 10;
                int row = (c >> 3) & 127;
                int seg = c & 7;
                const __nv_bfloat16* src = (t == 0 ? khi : klo) + (size_t)(j0 + row) * HD + seg * 8;
                CP_ASYNC16(dst + t * ATT_KTILE + row * ATT_KROWB + seg * 16, src);
            } else {
                int cv = c - 2048;
                int row = cv >> 4;
                int seg = cv & 15;
                const __half* src = vts + (size_t)row * Sq + j0 + seg * 8;
                CP_ASYNC16(dst + ATT_VOFF + row * ATT_VROWB + seg * 16, src);
            }
        }
        CP_COMMIT();
    };

    load(0, 0);

    for (int t = 0; t < nchunks; t++) {
        const int s = t & 1;
        if (t + 1 < nchunks) { load(s ^ 1, t + 1); cp_wait<1>(); }
        else                 { cp_wait<0>(); }
        __syncthreads();

        const uint32_t st = sb + s * ATT_STAGEB;
        #pragma unroll
        for (int half = 0; half < 2; half++) {
            const int j0 = t * 128 + half * 64;
            if (j0 <= q0 + wm + 15) {
                float sc[8][4];
                #pragma unroll
                for (int n = 0; n < 8; n++)
                    #pragma unroll
                    for (int j = 0; j < 4; j++) sc[n][j] = 0.f;

                #pragma unroll
                for (int kb = 0; kb < 4; kb++) {
                    #pragma unroll
                    for (int nj = 0; nj < 4; nj++) {
                        uint32_t bh[4], bl[4];
                        uint32_t addr = st + (half * 64 + nj * 16 + b_row_add) * ATT_KROWB
                                        + (kb * 16 + b_col_add) * 2;
                        LDMATRIX_X4(bh, addr);
                        LDMATRIX_X4(bl, addr + ATT_KTILE);
                        #pragma unroll
                        for (int hh = 0; hh < 2; hh++) {
                            int n = nj * 2 + hh;
                            MMA_BF16(sc[n], qa_hi[kb], bh[hh*2], bh[hh*2+1]);
                            MMA_BF16(sc[n], qa_hi[kb], bl[hh*2], bl[hh*2+1]);
                            MMA_BF16(sc[n], qa_lo[kb], bh[hh*2], bh[hh*2+1]);
                        }
                    }
                }

                if (j0 + 63 > q0 + wm) {
                    int r0 = q0 + wm + g;
                    #pragma unroll
                    for (int n = 0; n < 8; n++) {
                        int cb = j0 + n * 8 + tg * 2;
                        if (cb     > r0)     sc[n][0] = -1e30f;
                        if (cb + 1 > r0)     sc[n][1] = -1e30f;
                        if (cb     > r0 + 8) sc[n][2] = -1e30f;
                        if (cb + 1 > r0 + 8) sc[n][3] = -1e30f;
                    }
                }

                float mx0 = -1e30f, mx1 = -1e30f;
                #pragma unroll
                for (int n = 0; n < 8; n++) {
                    mx0 = fmaxf(mx0, fmaxf(sc[n][0], sc[n][1]));
                    mx1 = fmaxf(mx1, fmaxf(sc[n][2], sc[n][3]));
                }
                mx0 = fmaxf(mx0, __shfl_xor_sync(0xffffffffu, mx0, 1));
                mx0 = fmaxf(mx0, __shfl_xor_sync(0xffffffffu, mx0, 2));
                mx1 = fmaxf(mx1, __shfl_xor_sync(0xffffffffu, mx1, 1));
                mx1 = fmaxf(mx1, __shfl_xor_sync(0xffffffffu, mx1, 2));

                float nm0 = fmaxf(m0, mx0), nm1 = fmaxf(m1, mx1);
                float corr0 = ex2(m0 - nm0), corr1 = ex2(m1 - nm1);
                m0 = nm0; m1 = nm1;

                float s0 = 0.f, s1 = 0.f;
                #pragma unroll
                for (int n = 0; n < 8; n++) {
                    sc[n][0] = ex2(sc[n][0] - nm0);
                    sc[n][1] = ex2(sc[n][1] - nm0);
                    sc[n][2] = ex2(sc[n][2] - nm1);
                    sc[n][3] = ex2(sc[n][3] - nm1);
                    s0 += sc[n][0] + sc[n][1];
                    s1 += sc[n][2] + sc[n][3];
                }
                s0 += __shfl_xor_sync(0xffffffffu, s0, 1);
                s0 += __shfl_xor_sync(0xffffffffu, s0, 2);
                s1 += __shfl_xor_sync(0xffffffffu, s1, 1);
                s1 += __shfl_xor_sync(0xffffffffu, s1, 2);
                l0 = l0 * corr0 + s0;
                l1 = l1 * corr1 + s1;

                #pragma unroll
                for (int n = 0; n < 8; n++) {
                    oacc[n][0] *= corr0; oacc[n][1] *= corr0;
                    oacc[n][2] *= corr1; oacc[n][3] *= corr1;
                }

                uint32_t pa_hi[4][4], pa_lo[4][4];
                #pragma unroll
                for (int kb = 0; kb < 4; kb++) {
                    #pragma unroll
                    for (int hh = 0; hh < 2; hh++) {
                        int n = 2 * kb + hh;
                        uint32_t h0 = packh(sc[n][0], sc[n][1]);
                        uint32_t h1 = packh(sc[n][2], sc[n][3]);
                        float2 u0 = unpackh(h0), u1 = unpackh(h1);
                        pa_hi[kb][hh * 2 + 0] = h0;
                        pa_hi[kb][hh * 2 + 1] = h1;
                        pa_lo[kb][hh * 2 + 0] = packh(sc[n][0] - u0.x, sc[n][1] - u0.y);
                        pa_lo[kb][hh * 2 + 1] = packh(sc[n][2] - u1.x, sc[n][3] - u1.y);
                    }
                }

                #pragma unroll
                for (int kb = 0; kb < 4; kb++) {
                    #pragma unroll
                    for (int dg = 0; dg < 4; dg++) {
                        uint32_t vh[4];
                        uint32_t addr = st + ATT_VOFF + (dg * 16 + b_row_add) * ATT_VROWB
                                        + (half * 64 + kb * 16 + b_col_add) * 2;
                        LDMATRIX_X4(vh, addr);
                        #pragma unroll
                        for (int hh = 0; hh < 2; hh++) {
                            int n = dg * 2 + hh;
                            MMA_F16(oacc[n], pa_hi[kb], vh[hh*2], vh[hh*2+1]);
                            MMA_F16(oacc[n], pa_lo[kb], vh[hh*2], vh[hh*2+1]);
                        }
                    }
                }
            }
        }
        __syncthreads();
    }

    float inv0 = 1.f / l0, inv1 = 1.f / l1;
    int row0 = q0 + wm + g;
    #pragma unroll
    for (int n = 0; n < 8; n++) {
        int col = h * HD + n * 8 + tg * 2;
        size_t o0 = (size_t)(b * Sq + row0) * N_HID + col;
        size_t o1 = (size_t)(b * Sq + row0 + 8) * N_HID + col;
        float a0 = oacc[n][0] * inv0, a1 = oacc[n][1] * inv0;
        float a2 = oacc[n][2] * inv1, a3 = oacc[n][3] * inv1;
        uint32_t h0 = packh(a0, a1), h1 = packh(a2, a3);
        float2 u0 = unpackh(h0), u1 = unpackh(h1);
        *(uint32_t*)(g_attn_hi + o0) = h0;
        *(uint32_t*)(g_attn_hi + o1) = h1;
        *(uint32_t*)(g_attn_lo + o0) = packh(a0 - u0.x, a1 - u0.y);
        *(uint32_t*)(g_attn_lo + o1) = packh(a2 - u1.x, a3 - u1.y);
    }
}

// ---------------------------------------------------------------------------
// Launch pipeline
// ---------------------------------------------------------------------------
extern "C" void kernel_launch(void* const* d_in, const int* in_sizes, int n_in,
                              void* d_out, int out_size)
{
    const int*   positions = (const int*)d_in[0];
    const float* hidden    = (const float*)d_in[1];
    const float* Wqkv      = (const float*)d_in[2];
    const float* Wo        = (const float*)d_in[3];
    float*       out       = (float*)d_out;

    __half *hid_hi, *hid_lo, *wqkvT, *woT, *attn_hi, *attn_lo;
    cudaGetSymbolAddress((void**)&hid_hi,  g_hid_hi);
    cudaGetSymbolAddress((void**)&hid_lo,  g_hid_lo);
    cudaGetSymbolAddress((void**)&wqkvT,   g_wqkvT);
    cudaGetSymbolAddress((void**)&woT,     g_woT);
    cudaGetSymbolAddress((void**)&attn_hi, g_attn_hi);
    cudaGetSymbolAddress((void**)&attn_lo, g_attn_lo);

    cudaFuncSetAttribute(gemm_h,   cudaFuncAttributeMaxDynamicSharedMemorySize, GEMM_SMEM);
    cudaFuncSetAttribute(attn_mma, cudaFuncAttributeMaxDynamicSharedMemorySize, ATT_SMEM);

    static cudaStream_t s2 = nullptr;
    static cudaEvent_t eFork = nullptr, eQkvW = nullptr, eWoW = nullptr;
    if (!s2) {
        cudaStreamCreateWithFlags(&s2, cudaStreamNonBlocking);
        cudaEventCreateWithFlags(&eFork, cudaEventDisableTiming);
        cudaEventCreateWithFlags(&eQkvW, cudaEventDisableTiming);
        cudaEventCreateWithFlags(&eWoW,  cudaEventDisableTiming);
    }

    const int GEMM_GRID = 296;   // 148 SMs x 2 CTAs

    cudaEventRecord(eFork, 0);
    cudaStreamWaitEvent(s2, eFork, 0);
    transpose_h<<<dim3(QKVW / 32, HIDD / 32), dim3(32, 8), 0, s2>>>(Wqkv, wqkvT, HIDD, QKVW);
    cudaEventRecord(eQkvW, s2);
    transpose_h<<<dim3(HIDD / 32, N_HID / 32), dim3(32, 8), 0, s2>>>(Wo, woT, N_HID, HIDD);
    cudaEventRecord(eWoW, s2);

    {
        int n4 = (MROWS * HIDD) / 4;
        convert_split_h<<<(n4 + 255) / 256, 256>>>(hidden, hid_hi, hid_lo, n4);
    }
    cudaStreamWaitEvent(0, eQkvW, 0);
    // QKV projection: fully fused epilogue (Q/K RoPE + split, V transpose)
    gemm_h<<<GEMM_GRID, 256, GEMM_SMEM>>>(
        MROWS, QKVW, HIDD, hid_hi, hid_lo, wqkvT, nullptr, positions, 1);

    // Flash attention (reads g_q_hi/lo, g_k_hi/lo, g_vt)
    attn_mma<<<dim3(Sq / 128, NH, Bq), 256, ATT_SMEM>>>();

    cudaStreamWaitEvent(0, eWoW, 0);
    // Output projection (plain fp32 epilogue)
    gemm_h<<<GEMM_GRID, 256, GEMM_SMEM>>>(
        MROWS, HIDD, N_HID, attn_hi, attn_lo, woT, out, nullptr, 0);
}

// round 17
// speedup vs baseline: 1.0986x; 1.0986x over previous
#include <cuda_runtime.h>
#include <cuda_bf16.h>
#include <cuda_fp16.h>
#include <cstdint>
#include <cstddef>

#define Bq   2
#define Sq   2048
#define HIDD 2048
#define NH   32
#define NKV  8
#define HD   64
#define QKVW ((NH + 2 * NKV) * HD)   /* 3072 */
#define GROUP (NH / NKV)             /* 4 */
#define SCALE 0.125f
#define LOG2E 1.4426950408889634f
#define QSCALE (SCALE * LOG2E)
#define ROPE_C 0.28782313662425575f  /* ln(10000)/32 */

#define MROWS   (Bq * Sq)            /* 4096 */
#define N_HID   (NH * HD)            /* 2048 */

// ---------------------------------------------------------------------------
// Scratch (device globals)
// ---------------------------------------------------------------------------
__device__ __half g_hid_hi [(size_t)MROWS * HIDD];
__device__ __half g_hid_lo [(size_t)MROWS * HIDD];
__device__ __half g_wqkvT  [(size_t)QKVW * HIDD];
__device__ __half g_woT    [(size_t)HIDD * N_HID];
__device__ __half g_attn_hi[(size_t)MROWS * N_HID];
__device__ __half g_attn_lo[(size_t)MROWS * N_HID];

// Q (RoPE'd, scaled) bf16 hi/lo: [b, h, s, d]
__device__ __nv_bfloat16 g_q_hi [(size_t)Bq * NH * Sq * HD];
__device__ __nv_bfloat16 g_q_lo [(size_t)Bq * NH * Sq * HD];
// K (RoPE'd) bf16 hi/lo: [b, hk, s, d]; V^T fp16: [b, hk, d, s]
__device__ __nv_bfloat16 g_k_hi [(size_t)Bq * NKV * Sq * HD];
__device__ __nv_bfloat16 g_k_lo [(size_t)Bq * NKV * Sq * HD];
__device__ __half        g_vt   [(size_t)Bq * NKV * HD * Sq];

// ---------------------------------------------------------------------------
// Helpers
// ---------------------------------------------------------------------------
__device__ __forceinline__ uint32_t smem_u32(const void* p) {
    uint32_t a;
    asm("{ .reg .u64 t; cvta.to.shared.u64 t, %1; cvt.u32.u64 %0, t; }"
        : "=r"(a) : "l"(p));
    return a;
}
__device__ __forceinline__ uint32_t packbf(float x, float y) {   // lo=x, hi=y
    uint32_t r;
    asm("cvt.rn.bf16x2.f32 %0, %1, %2;" : "=r"(r) : "f"(y), "f"(x));
    return r;
}
__device__ __forceinline__ float2 unpackbf(uint32_t v) {
    __nv_bfloat162 t = *reinterpret_cast<__nv_bfloat162*>(&v);
    return make_float2(__bfloat162float(t.x), __bfloat162float(t.y));
}
__device__ __forceinline__ uint32_t packh(float x, float y) {    // lo=x, hi=y
    uint32_t r;
    asm("cvt.rn.f16x2.f32 %0, %1, %2;" : "=r"(r) : "f"(y), "f"(x));
    return r;
}
__device__ __forceinline__ float2 unpackh(uint32_t v) {
    __half2 t = *reinterpret_cast<__half2*>(&v);
    return make_float2(__half2float(t.x), __half2float(t.y));
}
__device__ __forceinline__ float ex2(float x) {
    float r; asm("ex2.approx.f32 %0, %1;" : "=f"(r) : "f"(x)); return r;
}

#define MMA_BF16(c, a, br0, br1) \
    asm volatile("mma.sync.aligned.m16n8k16.row.col.f32.bf16.bf16.f32 " \
        "{%0,%1,%2,%3}, {%4,%5,%6,%7}, {%8,%9}, {%0,%1,%2,%3};" \
        : "+f"((c)[0]), "+f"((c)[1]), "+f"((c)[2]), "+f"((c)[3]) \
        : "r"((a)[0]), "r"((a)[1]), "r"((a)[2]), "r"((a)[3]), "r"(br0), "r"(br1))

#define MMA_F16(c, a, br0, br1) \
    asm volatile("mma.sync.aligned.m16n8k16.row.col.f32.f16.f16.f32 " \
        "{%0,%1,%2,%3}, {%4,%5,%6,%7}, {%8,%9}, {%0,%1,%2,%3};" \
        : "+f"((c)[0]), "+f"((c)[1]), "+f"((c)[2]), "+f"((c)[3]) \
        : "r"((a)[0]), "r"((a)[1]), "r"((a)[2]), "r"((a)[3]), "r"(br0), "r"(br1))

#define LDMATRIX_X4(r, addr) \
    asm volatile("ldmatrix.sync.aligned.m8n8.x4.shared.b16 {%0,%1,%2,%3}, [%4];" \
        : "=r"((r)[0]), "=r"((r)[1]), "=r"((r)[2]), "=r"((r)[3]) : "r"(addr))

#define CP_ASYNC16(saddr, gptr) \
    asm volatile("cp.async.cg.shared.global [%0], [%1], 16;" :: "r"(saddr), "l"(gptr))
#define CP_COMMIT() asm volatile("cp.async.commit_group;" ::: "memory")
template <int N> __device__ __forceinline__ void cp_wait() {
    asm volatile("cp.async.wait_group %0;" :: "n"(N) : "memory");
}

// ---------------------------------------------------------------------------
// fp32 -> fp16 hi/lo split (8 elements/thread, 16B stores)
// ---------------------------------------------------------------------------
__global__ void convert_split_h(const float* __restrict__ x,
                                __half* __restrict__ hi,
                                __half* __restrict__ lo, int n8)
{
    int i = blockIdx.x * blockDim.x + threadIdx.x;
    if (i >= n8) return;
    float4 v0 = ((const float4*)x)[2 * i];
    float4 v1 = ((const float4*)x)[2 * i + 1];
    uint32_t h01 = packh(v0.x, v0.y), h23 = packh(v0.z, v0.w);
    uint32_t h45 = packh(v1.x, v1.y), h67 = packh(v1.z, v1.w);
    float2 f01 = unpackh(h01), f23 = unpackh(h23);
    float2 f45 = unpackh(h45), f67 = unpackh(h67);
    uint32_t l01 = packh(v0.x - f01.x, v0.y - f01.y);
    uint32_t l23 = packh(v0.z - f23.x, v0.w - f23.y);
    uint32_t l45 = packh(v1.x - f45.x, v1.y - f45.y);
    uint32_t l67 = packh(v1.z - f67.x, v1.w - f67.y);
    ((uint4*)hi)[i] = make_uint4(h01, h23, h45, h67);
    ((uint4*)lo)[i] = make_uint4(l01, l23, l45, l67);
}

// ---------------------------------------------------------------------------
// Transpose fp32 B[R x C] -> fp16 [C x R]
// ---------------------------------------------------------------------------
__global__ void transpose_h(const float* __restrict__ B,
                            __half* __restrict__ T, int R, int C)
{
    __shared__ float t[32][33];
    int x = blockIdx.x * 32 + threadIdx.x;
    int y = blockIdx.y * 32 + threadIdx.y;
    #pragma unroll
    for (int j = 0; j < 32; j += 8)
        t[threadIdx.y + j][threadIdx.x] = B[(size_t)(y + j) * C + x];
    __syncthreads();
    int ox = blockIdx.y * 32 + threadIdx.x;
    int oy = blockIdx.x * 32 + threadIdx.y;
    #pragma unroll
    for (int j = 0; j < 32; j += 8)
        T[(size_t)(oy + j) * R + ox] = __float2half_rn(t[threadIdx.x][threadIdx.y + j]);
}

// ---------------------------------------------------------------------------
// Persistent GEMM (R15-proven): C = (Ahi+Alo) * B^T (fp16 2-product).
// CTA tile 128x128, 8 warps, K-chunk 64, 2-stage, 2 CTAs/SM.
// fuse_kv epilogue: Q RoPE+scale+bf16 split, K RoPE+bf16 split, V transpose.
// ---------------------------------------------------------------------------
#define ROWB       144           /* 128B data + 16B pad */
#define TILEB      (128 * ROWB)  /* 18432 */
#define STAGEB     (3 * TILEB)   /* 55296 */
#define GEMM_SMEM  (2 * STAGEB)  /* 110592 */

__global__ __launch_bounds__(256, 2) void gemm_h(
    int M, int N, int K,
    const __half* __restrict__ Ahi, const __half* __restrict__ Alo,
    const __half* __restrict__ B,
    float* __restrict__ C,
    const int* __restrict__ positions, int fuse_kv)
{
    extern __shared__ char smem[];
    const uint32_t sbase = smem_u32(smem);
    const int tid  = threadIdx.x;
    const int wid  = tid >> 5;
    const int lane = tid & 31;
    const int wm = (wid >> 1) * 32;
    const int wn = (wid & 1) * 64;

    const int q  = lane >> 3;
    const int ri = lane & 7;
    const int a_row_add = ((q & 1) << 3) + ri;
    const int a_col_add = (q >> 1) << 3;
    const int b_row_add = ((q >> 1) << 3) + ri;
    const int b_col_add = (q & 1) << 3;
    const int go = lane >> 2;
    const int tg = lane & 3;

    const int nx = N >> 7;
    const int ntiles = (M >> 7) * nx;
    const int NC = K >> 6;

    for (int tile = blockIdx.x; tile < ntiles; tile += gridDim.x) {
        const int m0 = (tile / nx) * 128;
        const int n0 = (tile % nx) * 128;

        const __half* srcs[3] = {
            Ahi + (size_t)m0 * K, Alo + (size_t)m0 * K, B + (size_t)n0 * K
        };

        float acc[2][8][4];
        #pragma unroll
        for (int mi = 0; mi < 2; mi++)
            #pragma unroll
            for (int ni = 0; ni < 8; ni++)
                #pragma unroll
                for (int c = 0; c < 4; c++) acc[mi][ni][c] = 0.f;

        auto load_chunk = [&](int stage, int k0) {
            uint32_t sdst = sbase + stage * STAGEB;
            #pragma unroll
            for (int t = 0; t < 3; t++) {
                #pragma unroll
                for (int u = 0; u < 4; u++) {
                    int idx = tid + u * 256;
                    int row = idx >> 3;
                    int seg = idx & 7;
                    const __half* g = srcs[t] + (size_t)row * K + k0 + seg * 8;
                    CP_ASYNC16(sdst + t * TILEB + row * ROWB + seg * 16, g);
                }
            }
            CP_COMMIT();
        };

        __syncthreads();   // protect smem reuse across tiles
        load_chunk(0, 0);

        for (int i = 0; i < NC; i++) {
            const int s = i & 1;
            if (i + 1 < NC) { load_chunk(s ^ 1, (i + 1) << 6); cp_wait<1>(); }
            else           { cp_wait<0>(); }
            __syncthreads();

            const uint32_t st = sbase + s * STAGEB;
            #pragma unroll
            for (int kk = 0; kk < 64; kk += 16) {
                uint32_t a_hi[2][4], a_lo[2][4];
                #pragma unroll
                for (int mi = 0; mi < 2; mi++) {
                    int row = wm + mi * 16 + a_row_add;
                    int col = kk + a_col_add;
                    LDMATRIX_X4(a_hi[mi], st + 0 * TILEB + row * ROWB + col * 2);
                    LDMATRIX_X4(a_lo[mi], st + 1 * TILEB + row * ROWB + col * 2);
                }
                #pragma unroll
                for (int nj = 0; nj < 4; nj++) {
                    uint32_t bf[4];
                    int row = wn + nj * 16 + b_row_add;
                    int col = kk + b_col_add;
                    LDMATRIX_X4(bf, st + 2 * TILEB + row * ROWB + col * 2);
                    #pragma unroll
                    for (int mi = 0; mi < 2; mi++) {
                        #pragma unroll
                        for (int hh = 0; hh < 2; hh++) {
                            int ni = nj * 2 + hh;
                            MMA_F16(acc[mi][ni], a_hi[mi], bf[hh*2], bf[hh*2+1]);
                            MMA_F16(acc[mi][ni], a_lo[mi], bf[hh*2], bf[hh*2+1]);
                        }
                    }
                }
            }
            __syncthreads();
        }

        // ------------------- epilogue -------------------
        const int colbase = n0 + wn;       // warp's 64-col region start
        if (!fuse_kv) {
            #pragma unroll
            for (int mi = 0; mi < 2; mi++) {
                #pragma unroll
                for (int ni = 0; ni < 8; ni++) {
                    int row = m0 + wm + mi * 16 + go;
                    int col = n0 + wn + ni * 8 + tg * 2;
                    *(float2*)(C + (size_t)row * N + col)       = make_float2(acc[mi][ni][0], acc[mi][ni][1]);
                    *(float2*)(C + (size_t)(row + 8) * N + col) = make_float2(acc[mi][ni][2], acc[mi][ni][3]);
                }
            }
        } else if (colbase < NH * HD) {
            // Q region: RoPE + QSCALE + bf16 hi/lo to [b, h, s, d]
            const int hq = colbase >> 6;
            #pragma unroll
            for (int mi = 0; mi < 2; mi++) {
                #pragma unroll
                for (int rs = 0; rs < 2; rs++) {
                    int m = m0 + wm + mi * 16 + go + rs * 8;
                    float pos = (float)positions[m];
                    int bb = m >> 11, ss = m & (Sq - 1);
                    size_t qb = ((size_t)(bb * NH + hq) * Sq + ss) * HD;
                    #pragma unroll
                    for (int ni = 0; ni < 4; ni++) {
                        int d0 = ni * 8 + tg * 2;
                        float x1a = acc[mi][ni][rs * 2 + 0],     x1b = acc[mi][ni][rs * 2 + 1];
                        float x2a = acc[mi][ni + 4][rs * 2 + 0], x2b = acc[mi][ni + 4][rs * 2 + 1];
                        float sna, csa, snb, csb;
                        sincosf(pos * __expf(-(float)d0 * ROPE_C), &sna, &csa);
                        sincosf(pos * __expf(-(float)(d0 + 1) * ROPE_C), &snb, &csb);
                        float o1a = (x1a * csa - x2a * sna) * QSCALE, o2a = (x2a * csa + x1a * sna) * QSCALE;
                        float o1b = (x1b * csb - x2b * snb) * QSCALE, o2b = (x2b * csb + x1b * snb) * QSCALE;
                        uint32_t h1 = packbf(o1a, o1b); float2 u1 = unpackbf(h1);
                        uint32_t h2 = packbf(o2a, o2b); float2 u2 = unpackbf(h2);
                        *(uint32_t*)(g_q_hi + qb + d0)      = h1;
                        *(uint32_t*)(g_q_lo + qb + d0)      = packbf(o1a - u1.x, o1b - u1.y);
                        *(uint32_t*)(g_q_hi + qb + d0 + 32) = h2;
                        *(uint32_t*)(g_q_lo + qb + d0 + 32) = packbf(o2a - u2.x, o2b - u2.y);
                    }
                }
            }
        } else if (colbase < (NH + NKV) * HD) {
            // K region: RoPE + bf16 hi/lo direct write
            const int hk = (colbase - NH * HD) >> 6;
            #pragma unroll
            for (int mi = 0; mi < 2; mi++) {
                #pragma unroll
                for (int rs = 0; rs < 2; rs++) {
                    int m = m0 + wm + mi * 16 + go + rs * 8;
                    float pos = (float)positions[m];
                    int bb = m >> 11, ss = m & (Sq - 1);
                    size_t kb = ((size_t)(bb * NKV + hk) * Sq + ss) * HD;
                    #pragma unroll
                    for (int ni = 0; ni < 4; ni++) {
                        int d0 = ni * 8 + tg * 2;
                        float x1a = acc[mi][ni][rs * 2 + 0],     x1b = acc[mi][ni][rs * 2 + 1];
                        float x2a = acc[mi][ni + 4][rs * 2 + 0], x2b = acc[mi][ni + 4][rs * 2 + 1];
                        float sna, csa, snb, csb;
                        sincosf(pos * __expf(-(float)d0 * ROPE_C), &sna, &csa);
                        sincosf(pos * __expf(-(float)(d0 + 1) * ROPE_C), &snb, &csb);
                        float o1a = x1a * csa - x2a * sna, o2a = x2a * csa + x1a * sna;
                        float o1b = x1b * csb - x2b * snb, o2b = x2b * csb + x1b * snb;
                        uint32_t h1 = packbf(o1a, o1b); float2 u1 = unpackbf(h1);
                        uint32_t h2 = packbf(o2a, o2b); float2 u2 = unpackbf(h2);
                        *(uint32_t*)(g_k_hi + kb + d0)      = h1;
                        *(uint32_t*)(g_k_lo + kb + d0)      = packbf(o1a - u1.x, o1b - u1.y);
                        *(uint32_t*)(g_k_hi + kb + d0 + 32) = h2;
                        *(uint32_t*)(g_k_lo + kb + d0 + 32) = packbf(o2a - u2.x, o2b - u2.y);
                    }
                }
            }
        } else {
            // V region: transposed single-fp16 write
            const int hk = (colbase - (NH + NKV) * HD) >> 6;
            #pragma unroll
            for (int mi = 0; mi < 2; mi++) {
                #pragma unroll
                for (int rs = 0; rs < 2; rs++) {
                    int m = m0 + wm + mi * 16 + go + rs * 8;
                    int bb = m >> 11, ss = m & (Sq - 1);
                    size_t vb = (size_t)(bb * NKV + hk) * HD * Sq + ss;
                    #pragma unroll
                    for (int ni = 0; ni < 8; ni++) {
                        int d0 = ni * 8 + tg * 2;
                        g_vt[vb + (size_t)d0 * Sq]       = __float2half_rn(acc[mi][ni][rs * 2 + 0]);
                        g_vt[vb + (size_t)(d0 + 1) * Sq] = __float2half_rn(acc[mi][ni][rs * 2 + 1]);
                    }
                }
            }
        }
    }
}

// ---------------------------------------------------------------------------
// mma.sync flash attention; Q pre-RoPE'd/scaled/split by the QKV GEMM.
// ---------------------------------------------------------------------------
#define ATT_KROWB  144
#define ATT_KTILE  (128 * ATT_KROWB)
#define ATT_VROWB  272
#define ATT_VTILE  (64 * ATT_VROWB)
#define ATT_VOFF   (2 * ATT_KTILE)
#define ATT_STAGEB (ATT_VOFF + ATT_VTILE)
#define ATT_SMEM   (2 * ATT_STAGEB)

__global__ __launch_bounds__(256, 1) void attn_mma()
{
    const int qt = (int)gridDim.x - 1 - (int)blockIdx.x;
    const int h  = blockIdx.y;
    const int b  = blockIdx.z;
    const int hk = h / GROUP;
    const int q0 = qt * 128;

    extern __shared__ char smem[];
    const uint32_t sb = smem_u32(smem);
    const int tid  = threadIdx.x;
    const int wid  = tid >> 5;
    const int lane = tid & 31;
    const int wm   = wid * 16;
    const int g  = lane >> 2;
    const int tg = lane & 3;
    const int q  = lane >> 3;
    const int ri = lane & 7;
    const int b_row_add = ((q >> 1) << 3) + ri;
    const int b_col_add = (q & 1) << 3;

    // ---- Q fragments: direct uint32 loads ----
    uint32_t qa_hi[4][4], qa_lo[4][4];
    {
        size_t qb = ((size_t)(b * NH + h) * Sq + q0 + wm) * HD;
        #pragma unroll
        for (int kb = 0; kb < 4; kb++) {
            #pragma unroll
            for (int p = 0; p < 4; p++) {
                int row = g + (p & 1) * 8;
                int col = kb * 16 + tg * 2 + ((p >> 1) << 3);
                size_t off = qb + (size_t)row * HD + col;
                qa_hi[kb][p] = *(const uint32_t*)(g_q_hi + off);
                qa_lo[kb][p] = *(const uint32_t*)(g_q_lo + off);
            }
        }
    }

    float oacc[8][4];
    #pragma unroll
    for (int n = 0; n < 8; n++)
        #pragma unroll
        for (int j = 0; j < 4; j++) oacc[n][j] = 0.f;
    float m0 = -1e30f, m1 = -1e30f, l0 = 0.f, l1 = 0.f;

    const __nv_bfloat16* khi = g_k_hi + (size_t)(b * NKV + hk) * Sq * HD;
    const __nv_bfloat16* klo = g_k_lo + (size_t)(b * NKV + hk) * Sq * HD;
    const __half*        vts = g_vt   + (size_t)(b * NKV + hk) * HD * Sq;

    const int nchunks = qt + 1;

    auto load = [&](int stg, int ct) {
        uint32_t dst = sb + stg * ATT_STAGEB;
        int j0 = ct * 128;
        #pragma unroll
        for (int k = 0; k < 12; k++) {
            int c = tid + k * 256;
            if (c < 2048) {
                int t = c >> 10;
                int row = (c >> 3) & 127;
                int seg = c & 7;
                const __nv_bfloat16* src = (t == 0 ? khi : klo) + (size_t)(j0 + row) * HD + seg * 8;
                CP_ASYNC16(dst + t * ATT_KTILE + row * ATT_KROWB + seg * 16, src);
            } else {
                int cv = c - 2048;
                int row = cv >> 4;
                int seg = cv & 15;
                const __half* src = vts + (size_t)row * Sq + j0 + seg * 8;
                CP_ASYNC16(dst + ATT_VOFF + row * ATT_VROWB + seg * 16, src);
            }
        }
        CP_COMMIT();
    };

    load(0, 0);

    for (int t = 0; t < nchunks; t++) {
        const int s = t & 1;
        if (t + 1 < nchunks) { load(s ^ 1, t + 1); cp_wait<1>(); }
        else                 { cp_wait<0>(); }
        __syncthreads();

        const uint32_t st = sb + s * ATT_STAGEB;
        #pragma unroll
        for (int half = 0; half < 2; half++) {
            const int j0 = t * 128 + half * 64;
            if (j0 <= q0 + wm + 15) {
                float sc[8][4];
                #pragma unroll
                for (int n = 0; n < 8; n++)
                    #pragma unroll
                    for (int j = 0; j < 4; j++) sc[n][j] = 0.f;

                #pragma unroll
                for (int kb = 0; kb < 4; kb++) {
                    #pragma unroll
                    for (int nj = 0; nj < 4; nj++) {
                        uint32_t bh[4], bl[4];
                        uint32_t addr = st + (half * 64 + nj * 16 + b_row_add) * ATT_KROWB
                                        + (kb * 16 + b_col_add) * 2;
                        LDMATRIX_X4(bh, addr);
                        LDMATRIX_X4(bl, addr + ATT_KTILE);
                        #pragma unroll
                        for (int hh = 0; hh < 2; hh++) {
                            int n = nj * 2 + hh;
                            MMA_BF16(sc[n], qa_hi[kb], bh[hh*2], bh[hh*2+1]);
                            MMA_BF16(sc[n], qa_hi[kb], bl[hh*2], bl[hh*2+1]);
                            MMA_BF16(sc[n], qa_lo[kb], bh[hh*2], bh[hh*2+1]);
                        }
                    }
                }

                if (j0 + 63 > q0 + wm) {
                    int r0 = q0 + wm + g;
                    #pragma unroll
                    for (int n = 0; n < 8; n++) {
                        int cb = j0 + n * 8 + tg * 2;
                        if (cb     > r0)     sc[n][0] = -1e30f;
                        if (cb + 1 > r0)     sc[n][1] = -1e30f;
                        if (cb     > r0 + 8) sc[n][2] = -1e30f;
                        if (cb + 1 > r0 + 8) sc[n][3] = -1e30f;
                    }
                }

                float mx0 = -1e30f, mx1 = -1e30f;
                #pragma unroll
                for (int n = 0; n < 8; n++) {
                    mx0 = fmaxf(mx0, fmaxf(sc[n][0], sc[n][1]));
                    mx1 = fmaxf(mx1, fmaxf(sc[n][2], sc[n][3]));
                }
                mx0 = fmaxf(mx0, __shfl_xor_sync(0xffffffffu, mx0, 1));
                mx0 = fmaxf(mx0, __shfl_xor_sync(0xffffffffu, mx0, 2));
                mx1 = fmaxf(mx1, __shfl_xor_sync(0xffffffffu, mx1, 1));
                mx1 = fmaxf(mx1, __shfl_xor_sync(0xffffffffu, mx1, 2));

                float nm0 = fmaxf(m0, mx0), nm1 = fmaxf(m1, mx1);
                float corr0 = ex2(m0 - nm0), corr1 = ex2(m1 - nm1);
                m0 = nm0; m1 = nm1;

                float s0 = 0.f, s1 = 0.f;
                #pragma unroll
                for (int n = 0; n < 8; n++) {
                    sc[n][0] = ex2(sc[n][0] - nm0);
                    sc[n][1] = ex2(sc[n][1] - nm0);
                    sc[n][2] = ex2(sc[n][2] - nm1);
                    sc[n][3] = ex2(sc[n][3] - nm1);
                    s0 += sc[n][0] + sc[n][1];
                    s1 += sc[n][2] + sc[n][3];
                }
                s0 += __shfl_xor_sync(0xffffffffu, s0, 1);
                s0 += __shfl_xor_sync(0xffffffffu, s0, 2);
                s1 += __shfl_xor_sync(0xffffffffu, s1, 1);
                s1 += __shfl_xor_sync(0xffffffffu, s1, 2);
                l0 = l0 * corr0 + s0;
                l1 = l1 * corr1 + s1;

                #pragma unroll
                for (int n = 0; n < 8; n++) {
                    oacc[n][0] *= corr0; oacc[n][1] *= corr0;
                    oacc[n][2] *= corr1; oacc[n][3] *= corr1;
                }

                uint32_t pa_hi[4][4], pa_lo[4][4];
                #pragma unroll
                for (int kb = 0; kb < 4; kb++) {
                    #pragma unroll
                    for (int hh = 0; hh < 2; hh++) {
                        int n = 2 * kb + hh;
                        uint32_t h0 = packh(sc[n][0], sc[n][1]);
                        uint32_t h1 = packh(sc[n][2], sc[n][3]);
                        float2 u0 = unpackh(h0), u1 = unpackh(h1);
                        pa_hi[kb][hh * 2 + 0] = h0;
                        pa_hi[kb][hh * 2 + 1] = h1;
                        pa_lo[kb][hh * 2 + 0] = packh(sc[n][0] - u0.x, sc[n][1] - u0.y);
                        pa_lo[kb][hh * 2 + 1] = packh(sc[n][2] - u1.x, sc[n][3] - u1.y);
                    }
                }

                #pragma unroll
                for (int kb = 0; kb < 4; kb++) {
                    #pragma unroll
                    for (int dg = 0; dg < 4; dg++) {
                        uint32_t vh[4];
                        uint32_t addr = st + ATT_VOFF + (dg * 16 + b_row_add) * ATT_VROWB
                                        + (half * 64 + kb * 16 + b_col_add) * 2;
                        LDMATRIX_X4(vh, addr);
                        #pragma unroll
                        for (int hh = 0; hh < 2; hh++) {
                            int n = dg * 2 + hh;
                            MMA_F16(oacc[n], pa_hi[kb], vh[hh*2], vh[hh*2+1]);
                            MMA_F16(oacc[n], pa_lo[kb], vh[hh*2], vh[hh*2+1]);
                        }
                    }
                }
            }
        }
        __syncthreads();
    }

    float inv0 = 1.f / l0, inv1 = 1.f / l1;
    int row0 = q0 + wm + g;
    #pragma unroll
    for (int n = 0; n < 8; n++) {
        int col = h * HD + n * 8 + tg * 2;
        size_t o0 = (size_t)(b * Sq + row0) * N_HID + col;
        size_t o1 = (size_t)(b * Sq + row0 + 8) * N_HID + col;
        float a0 = oacc[n][0] * inv0, a1 = oacc[n][1] * inv0;
        float a2 = oacc[n][2] * inv1, a3 = oacc[n][3] * inv1;
        uint32_t h0 = packh(a0, a1), h1 = packh(a2, a3);
        float2 u0 = unpackh(h0), u1 = unpackh(h1);
        *(uint32_t*)(g_attn_hi + o0) = h0;
        *(uint32_t*)(g_attn_hi + o1) = h1;
        *(uint32_t*)(g_attn_lo + o0) = packh(a0 - u0.x, a1 - u0.y);
        *(uint32_t*)(g_attn_lo + o1) = packh(a2 - u1.x, a3 - u1.y);
    }
}

// ---------------------------------------------------------------------------
// Launch pipeline
// ---------------------------------------------------------------------------
extern "C" void kernel_launch(void* const* d_in, const int* in_sizes, int n_in,
                              void* d_out, int out_size)
{
    const int*   positions = (const int*)d_in[0];
    const float* hidden    = (const float*)d_in[1];
    const float* Wqkv      = (const float*)d_in[2];
    const float* Wo        = (const float*)d_in[3];
    float*       out       = (float*)d_out;

    __half *hid_hi, *hid_lo, *wqkvT, *woT, *attn_hi, *attn_lo;
    cudaGetSymbolAddress((void**)&hid_hi,  g_hid_hi);
    cudaGetSymbolAddress((void**)&hid_lo,  g_hid_lo);
    cudaGetSymbolAddress((void**)&wqkvT,   g_wqkvT);
    cudaGetSymbolAddress((void**)&woT,     g_woT);
    cudaGetSymbolAddress((void**)&attn_hi, g_attn_hi);
    cudaGetSymbolAddress((void**)&attn_lo, g_attn_lo);

    cudaFuncSetAttribute(gemm_h,   cudaFuncAttributeMaxDynamicSharedMemorySize, GEMM_SMEM);
    cudaFuncSetAttribute(attn_mma, cudaFuncAttributeMaxDynamicSharedMemorySize, ATT_SMEM);

    static cudaStream_t s2 = nullptr;
    static cudaEvent_t eFork = nullptr, eQkvW = nullptr, eWoW = nullptr;
    if (!s2) {
        cudaStreamCreateWithFlags(&s2, cudaStreamNonBlocking);
        cudaEventCreateWithFlags(&eFork, cudaEventDisableTiming);
        cudaEventCreateWithFlags(&eQkvW, cudaEventDisableTiming);
        cudaEventCreateWithFlags(&eWoW,  cudaEventDisableTiming);
    }

    const int GEMM_GRID = 296;   // 148 SMs x 2 CTAs

    cudaEventRecord(eFork, 0);
    cudaStreamWaitEvent(s2, eFork, 0);
    transpose_h<<<dim3(QKVW / 32, HIDD / 32), dim3(32, 8), 0, s2>>>(Wqkv, wqkvT, HIDD, QKVW);
    cudaEventRecord(eQkvW, s2);
    transpose_h<<<dim3(HIDD / 32, N_HID / 32), dim3(32, 8), 0, s2>>>(Wo, woT, N_HID, HIDD);
    cudaEventRecord(eWoW, s2);

    {
        int n8 = (MROWS * HIDD) / 8;
        convert_split_h<<<(n8 + 255) / 256, 256>>>(hidden, hid_hi, hid_lo, n8);
    }
    cudaStreamWaitEvent(0, eQkvW, 0);
    // QKV projection: fully fused epilogue (Q/K RoPE + split, V transpose)
    gemm_h<<<GEMM_GRID, 256, GEMM_SMEM>>>(
        MROWS, QKVW, HIDD, hid_hi, hid_lo, wqkvT, nullptr, positions, 1);

    // Flash attention (reads g_q_hi/lo, g_k_hi/lo, g_vt)
    attn_mma<<<dim3(Sq / 128, NH, Bq), 256, ATT_SMEM>>>();

    cudaStreamWaitEvent(0, eWoW, 0);
    // Output projection (plain fp32 epilogue)
    gemm_h<<<GEMM_GRID, 256, GEMM_SMEM>>>(
        MROWS, HIDD, N_HID, attn_hi, attn_lo, woT, out, nullptr, 0);
}